// round 14
// baseline (speedup 1.0000x reference)
#include <cuda_runtime.h>
#include <cuda_fp16.h>
#include <math.h>
#include <stdint.h>

#define NB   8
#define QL   2048
#define KLEN 2048
#define ED   1024

// ---------------- scratch arena ----------------
#define H_QIN  0ull
#define H_KVIN 16777216ull
#define H_WQ   33554432ull          // 4 x 1M half weights, contiguous (WQ WK WV WO)
#define H_WK   34603008ull
#define H_WV   35651584ull
#define H_WO   36700160ull
#define H_Q    37748736ull
#define H_K    54525952ull
#define H_V    71303168ull
#define H_VT   88080384ull
#define H_ATT  104857600ull
#define H_ATTD 138412032ull
#define OFF_S  79691776ull          // fp32 scores fallback (float offset)
__device__ float g_scratch[125829120ull];   // 480 MB

// ---------------- helpers ----------------
__device__ __forceinline__ uint32_t smem_u32(const void* p) {
    uint32_t a;
    asm("{ .reg .u64 t; cvta.to.shared.u64 t, %1; cvt.u32.u64 %0, t; }" : "=r"(a) : "l"(p));
    return a;
}
__device__ __forceinline__ void cp16(uint32_t s, const void* g) {
    asm volatile("cp.async.cg.shared.global [%0], [%1], 16;" :: "r"(s), "l"(g));
}
__device__ __forceinline__ void mma_f16(float* d, uint32_t a0, uint32_t a1,
                                        uint32_t a2, uint32_t a3,
                                        uint32_t b0, uint32_t b1) {
    asm volatile(
        "mma.sync.aligned.m16n8k16.row.col.f32.f16.f16.f32 "
        "{%0,%1,%2,%3}, {%4,%5,%6,%7}, {%8,%9}, {%0,%1,%2,%3};"
        : "+f"(d[0]), "+f"(d[1]), "+f"(d[2]), "+f"(d[3])
        : "r"(a0), "r"(a1), "r"(a2), "r"(a3), "r"(b0), "r"(b1));
}

// ---------------- fp16 mma.sync GEMM ----------------
// C = scale * A[M,K](ld=lda) @ B[N,K]^T(ld=ldb) (+bias). fp16 operands in arena.
// Optional N-split: CTAs with n0 >= nsplit write to cOff2/bias2 (col -= nsplit).
#define BM 128
#define BN 128
#define BKH 64
#define ROWB 160u
#define TILEB (128u * ROWB)
#define STAGEB (2u * TILEB)
#define SMEM_BYTES (2 * (int)STAGEB)   // 81920

template<int OUTH>
__global__ void __launch_bounds__(128, 2)
gemm_h(size_t aOff, int lda, size_t bOff, int ldb,
       const float* bias, const float* bias2,
       float* Cf, size_t cOff, size_t cOff2, int nsplit, int ldc,
       int Kd, float scale, size_t sA, size_t sB, size_t sC)
{
    extern __shared__ char smc[];
    const __half* Ap = (const __half*)g_scratch + aOff + (size_t)blockIdx.z * sA;
    const __half* Bp = (const __half*)g_scratch + bOff + (size_t)blockIdx.z * sB;

    const int tid  = threadIdx.x;
    const int lane = tid & 31;
    const int wid  = tid >> 5;
    const int wm   = wid >> 1;
    const int wn   = wid & 1;
    const int grp  = lane >> 2;
    const int t4   = lane & 3;
    const int m0   = blockIdx.y * BM;
    const int n0   = blockIdx.x * BN;
    const uint32_t sbase = smem_u32(smc);

    float acc[4][8][4];
#pragma unroll
    for (int a = 0; a < 4; a++)
#pragma unroll
        for (int b = 0; b < 8; b++)
#pragma unroll
            for (int c = 0; c < 4; c++) acc[a][b][c] = 0.f;

    auto issue_tile = [&](int k0, int stg) {
        const uint32_t aB = sbase + (uint32_t)stg * STAGEB;
        const uint32_t bB = aB + TILEB;
#pragma unroll
        for (int j = 0; j < 8; j++) {
            int f  = tid + j * 128;
            int r  = f >> 3;
            int c  = f & 7;
            cp16(aB + (uint32_t)r * ROWB + (uint32_t)c * 16u,
                 Ap + (size_t)(m0 + r) * lda + k0 + c * 8);
            cp16(bB + (uint32_t)r * ROWB + (uint32_t)c * 16u,
                 Bp + (size_t)(n0 + r) * ldb + k0 + c * 8);
        }
        asm volatile("cp.async.commit_group;" ::: "memory");
    };

    const int NT = Kd / BKH;
    issue_tile(0, 0);

    for (int i = 0; i < NT; i++) {
        if (i + 1 < NT) {
            issue_tile((i + 1) * BKH, (i + 1) & 1);
            asm volatile("cp.async.wait_group 1;" ::: "memory");
        } else {
            asm volatile("cp.async.wait_group 0;" ::: "memory");
        }
        __syncthreads();

        const char* As = smc + (i & 1) * STAGEB;
        const char* Bs = As + TILEB;

#pragma unroll
        for (int s = 0; s < 4; s++) {
            uint2 avLo[4], avHi[4], bv[8];
#pragma unroll
            for (int mt = 0; mt < 4; mt++) {
                const int row = wm * 64 + mt * 16 + grp;
                avLo[mt] = *reinterpret_cast<const uint2*>(
                    As + (size_t)row * ROWB + s * 32 + t4 * 8);
                avHi[mt] = *reinterpret_cast<const uint2*>(
                    As + (size_t)(row + 8) * ROWB + s * 32 + t4 * 8);
            }
#pragma unroll
            for (int nt = 0; nt < 8; nt++) {
                const int nr = wn * 64 + nt * 8 + grp;
                bv[nt] = *reinterpret_cast<const uint2*>(
                    Bs + (size_t)nr * ROWB + s * 32 + t4 * 8);
            }
#pragma unroll
            for (int mt = 0; mt < 4; mt++)
#pragma unroll
                for (int nt = 0; nt < 8; nt++)
                    mma_f16(acc[mt][nt],
                            avLo[mt].x, avHi[mt].x, avLo[mt].y, avHi[mt].y,
                            bv[nt].x, bv[nt].y);
        }
        __syncthreads();
    }

    // ---------------- epilogue ----------------
    size_t co = cOff;
    const float* bb = bias;
    int nbase = n0;
    if (n0 >= nsplit) { co = cOff2; bb = bias2; nbase = n0 - nsplit; }

    __half* Ch = (__half*)g_scratch + co + (size_t)blockIdx.z * sC;
    float* Cp = nullptr;
    if (!OUTH) Cp = (Cf ? Cf : (g_scratch + co)) + (size_t)blockIdx.z * sC;

#pragma unroll
    for (int mt = 0; mt < 4; mt++) {
        const int m = m0 + wm * 64 + mt * 16 + grp;
#pragma unroll
        for (int nt = 0; nt < 8; nt++) {
            const int n = nbase + wn * 64 + nt * 8 + t4 * 2;
            float bx = 0.f, by = 0.f;
            if (bb) {
                const float2 b2 = *reinterpret_cast<const float2*>(bb + n);
                bx = b2.x; by = b2.y;
            }
            const float v00 = acc[mt][nt][0] * scale + bx;
            const float v01 = acc[mt][nt][1] * scale + by;
            const float v10 = acc[mt][nt][2] * scale + bx;
            const float v11 = acc[mt][nt][3] * scale + by;
            if (OUTH) {
                *reinterpret_cast<__half2*>(Ch + (size_t)m * ldc + n) =
                    __floats2half2_rn(v00, v01);
                *reinterpret_cast<__half2*>(Ch + (size_t)(m + 8) * ldc + n) =
                    __floats2half2_rn(v10, v11);
            } else {
                *reinterpret_cast<float2*>(Cp + (size_t)m * ldc + n) = make_float2(v00, v01);
                *reinterpret_cast<float2*>(Cp + (size_t)(m + 8) * ldc + n) = make_float2(v10, v11);
            }
        }
    }
}

// ---------------- fp32 -> fp16 elementwise (z picks src tensor) ----------------
__global__ void __launch_bounds__(256)
cvt_f2h(const float* __restrict__ in0, const float* __restrict__ in1, size_t n)
{
    const float* in = blockIdx.z ? in1 : in0;
    const size_t hOff = H_QIN + (size_t)blockIdx.z * 16777216ull;
    const size_t i = ((size_t)blockIdx.x * 256 + threadIdx.x) * 4;
    if (i >= n) return;
    const float4 v = *reinterpret_cast<const float4*>(in + i);
    __half2* dst = reinterpret_cast<__half2*>((__half*)g_scratch + hOff + i);
    dst[0] = __floats2half2_rn(v.x, v.y);
    dst[1] = __floats2half2_rn(v.z, v.w);
}

// ---------------- fp32 -> fp16 weight transpose (z picks weight) ----------------
__global__ void __launch_bounds__(256)
cvtT_f2h(const float* W0, const float* W1, const float* W2, const float* W3)
{
    __shared__ float t[32][33];
    const float* in = (blockIdx.z == 0) ? W0 : (blockIdx.z == 1) ? W1
                    : (blockIdx.z == 2) ? W2 : W3;
    __half* op = (__half*)g_scratch + H_WQ + (size_t)blockIdx.z * 1048576ull;
    const int c0 = blockIdx.x * 32, r0 = blockIdx.y * 32;
    const int tx = threadIdx.x & 31, ty = threadIdx.x >> 5;
#pragma unroll
    for (int i = 0; i < 4; i++)
        t[ty + i * 8][tx] = in[(size_t)(r0 + ty + i * 8) * ED + c0 + tx];
    __syncthreads();
#pragma unroll
    for (int i = 0; i < 4; i++)
        op[(size_t)(c0 + ty + i * 8) * ED + r0 + tx] = __float2half(t[tx][ty + i * 8]);
}

// ---------------- fp16 transpose (V -> VT per batch) ----------------
__global__ void __launch_bounds__(256)
transpose_h(size_t inOff, size_t outOff, int R, int Cc, size_t sIn, size_t sOut)
{
    __shared__ __half t[32][34];
    const __half* ip = (const __half*)g_scratch + inOff + (size_t)blockIdx.z * sIn;
    __half*       op = (__half*)g_scratch + outOff + (size_t)blockIdx.z * sOut;
    const int c0 = blockIdx.x * 32, r0 = blockIdx.y * 32;
    const int tx = threadIdx.x & 31, ty = threadIdx.x >> 5;
#pragma unroll
    for (int i = 0; i < 4; i++)
        t[ty + i * 8][tx] = ip[(size_t)(r0 + ty + i * 8) * Cc + c0 + tx];
    __syncthreads();
#pragma unroll
    for (int i = 0; i < 4; i++)
        op[(size_t)(c0 + ty + i * 8) * R + r0 + tx] = t[tx][ty + i * 8];
}

// ---------------- masked softmax: vectorized, shuffle reductions ----------------
__global__ void __launch_bounds__(256)
softmax_mask_kernel(float* att, size_t attOff, const int* __restrict__ mask)
{
    float* base = att ? att : (g_scratch + attOff);
    const size_t row = blockIdx.x;
    float4* p4 = reinterpret_cast<float4*>(base + row * KLEN);
    const int4* m4 = reinterpret_cast<const int4*>(mask + row * KLEN);
    __half* ph = (__half*)g_scratch + H_ATT + row * KLEN;
    const int t = threadIdx.x;
    const int lane = t & 31, w = t >> 5;
    __shared__ float red[8];

    float4 v[2];
    float mx = -INFINITY;
#pragma unroll
    for (int i = 0; i < 2; i++) {
        const int c4 = t + i * 256;
        float4 x = p4[c4];
        const int4 mm = m4[c4];
        x.x = mm.x ? x.x : -INFINITY;
        x.y = mm.y ? x.y : -INFINITY;
        x.z = mm.z ? x.z : -INFINITY;
        x.w = mm.w ? x.w : -INFINITY;
        v[i] = x;
        mx = fmaxf(mx, fmaxf(fmaxf(x.x, x.y), fmaxf(x.z, x.w)));
    }
#pragma unroll
    for (int o = 16; o > 0; o >>= 1)
        mx = fmaxf(mx, __shfl_xor_sync(0xFFFFFFFFu, mx, o));
    if (lane == 0) red[w] = mx;
    __syncthreads();
    mx = red[lane & 7];
#pragma unroll
    for (int o = 4; o > 0; o >>= 1)
        mx = fmaxf(mx, __shfl_xor_sync(0xFFFFFFFFu, mx, o));

    float sum = 0.f;
#pragma unroll
    for (int i = 0; i < 2; i++) {
        v[i].x = __expf(v[i].x - mx); sum += v[i].x;
        v[i].y = __expf(v[i].y - mx); sum += v[i].y;
        v[i].z = __expf(v[i].z - mx); sum += v[i].z;
        v[i].w = __expf(v[i].w - mx); sum += v[i].w;
    }
#pragma unroll
    for (int o = 16; o > 0; o >>= 1)
        sum += __shfl_xor_sync(0xFFFFFFFFu, sum, o);
    __syncthreads();
    if (lane == 0) red[w] = sum;
    __syncthreads();
    sum = red[lane & 7];
#pragma unroll
    for (int o = 4; o > 0; o >>= 1)
        sum += __shfl_xor_sync(0xFFFFFFFFu, sum, o);
    const float inv = 1.f / sum;

#pragma unroll
    for (int i = 0; i < 2; i++) {
        const int c4 = t + i * 256;
        float4 x = v[i];
        x.x *= inv; x.y *= inv; x.z *= inv; x.w *= inv;
        p4[c4] = x;
        __half2 h0 = __floats2half2_rn(x.x, x.y);
        __half2 h1 = __floats2half2_rn(x.z, x.w);
        uint2 pk;
        pk.x = *reinterpret_cast<uint32_t*>(&h0);
        pk.y = *reinterpret_cast<uint32_t*>(&h1);
        *reinterpret_cast<uint2*>(ph + (size_t)c4 * 4) = pk;
    }
}

// ---------------- launch ----------------
extern "C" void kernel_launch(void* const* d_in, const int* in_sizes, int n_in,
                              void* d_out, int out_size)
{
    const float* query = (const float*)d_in[0];
    const float* keyv  = (const float*)d_in[1];
    const int*   mask  = (const int*)  d_in[2];
    const float* Wq = (const float*)d_in[3];
    const float* bq = (const float*)d_in[4];
    const float* Wk = (const float*)d_in[5];
    const float* bk = (const float*)d_in[6];
    const float* Wv = (const float*)d_in[7];
    const float* bv = (const float*)d_in[8];
    const float* Wo = (const float*)d_in[9];
    const float* bo = (const float*)d_in[10];

    float* out = (float*)d_out;
    const size_t out_elems = (size_t)NB * QL * ED;
    const bool attn_in_out = ((size_t)out_size > out_elems);
    float* attn_ptr = attn_in_out ? (out + out_elems) : nullptr;

    static bool attr_set = false;
    if (!attr_set) {
        cudaFuncSetAttribute(gemm_h<0>, cudaFuncAttributeMaxDynamicSharedMemorySize, SMEM_BYTES);
        cudaFuncSetAttribute(gemm_h<1>, cudaFuncAttributeMaxDynamicSharedMemorySize, SMEM_BYTES);
        attr_set = true;
    }

    const int M_ALL = NB * QL;
    const float scale = 1.0f / 32.0f;
    const size_t nIn = (size_t)M_ALL * ED;
    const int NOSPLIT = 1 << 30;

    dim3 cvtG((unsigned)(nIn / 4 / 256), 1, 2);
    dim3 tposeW(ED / 32, ED / 32, 4);
    dim3 tposeV(ED / 32, KLEN / 32, NB);
    dim3 gQ  (ED / BN,       M_ALL / BM, 1);     // (8, 128)
    dim3 gKV (2 * ED / BN,   M_ALL / BM, 1);     // (16, 128)
    dim3 gScore(KLEN / BN,   QL / BM,   NB);
    dim3 gAV (ED / BN,       QL / BM,   NB);

    // 0: converts (2 kernels)
    cvt_f2h<<<cvtG, 256>>>(query, keyv, nIn);
    cvtT_f2h<<<tposeW, 256>>>(Wq, Wk, Wv, Wo);

    // 1: Q projection
    gemm_h<1><<<gQ, 128, SMEM_BYTES>>>(H_QIN, ED, H_WQ, ED, bq, nullptr,
                                       nullptr, H_Q, 0, NOSPLIT, ED,
                                       ED, 1.0f, 0, 0, 0);
    // 2: K+V projections fused (B = [Wk^T ; Wv^T], split at n=1024)
    gemm_h<1><<<gKV, 128, SMEM_BYTES>>>(H_KVIN, ED, H_WK, ED, bk, bv,
                                        nullptr, H_K, H_V, ED, ED,
                                        ED, 1.0f, 0, 0, 0);

    // V^T per batch
    transpose_h<<<tposeV, 256>>>(H_V, H_VT, KLEN, ED,
                                 (size_t)KLEN * ED, (size_t)ED * KLEN);

    // 3: scores = scale * Q @ K^T -> fp32 attn
    gemm_h<0><<<gScore, 128, SMEM_BYTES>>>(H_Q, ED, H_K, ED, nullptr, nullptr,
                                           attn_ptr, OFF_S, 0, NOSPLIT, KLEN,
                                           ED, scale,
                                           (size_t)QL * ED, (size_t)KLEN * ED,
                                           (size_t)QL * KLEN);

    // 4: masked softmax (fp32 in place + fp16 copy)
    softmax_mask_kernel<<<NB * QL, 256>>>(attn_ptr, OFF_S, mask);

    // 5: attended = attn @ V -> fp16
    gemm_h<1><<<gAV, 128, SMEM_BYTES>>>(H_ATT, KLEN, H_VT, KLEN, nullptr, nullptr,
                                        nullptr, H_ATTD, 0, NOSPLIT, ED,
                                        KLEN, 1.0f,
                                        (size_t)QL * KLEN, (size_t)ED * KLEN,
                                        (size_t)QL * ED);

    // 6: out = attended @ Wo + bo -> fp32 d_out
    gemm_h<0><<<gQ, 128, SMEM_BYTES>>>(H_ATTD, ED, H_WO, ED, bo, nullptr,
                                       out, 0, 0, NOSPLIT, ED,
                                       ED, 1.0f, 0, 0, 0);
}

// round 15
// speedup vs baseline: 1.4358x; 1.4358x over previous
#include <cuda_runtime.h>
#include <cuda_fp16.h>
#include <math.h>
#include <stdint.h>

#define NB   8
#define QL   2048
#define KLEN 2048
#define ED   1024

// ---------------- scratch arena ----------------
#define H_QIN  0ull
#define H_KVIN 16777216ull
#define H_WQ   33554432ull
#define H_WK   34603008ull
#define H_WV   35651584ull
#define H_WO   36700160ull
#define H_Q    37748736ull
#define H_K    54525952ull
#define H_V    71303168ull
#define H_VT   88080384ull
#define H_ATT  104857600ull
#define H_ATTD 138412032ull
#define OFF_S  79691776ull          // fp32 scores fallback (float offset)
__device__ float g_scratch[125829120ull];   // 480 MB

// ---------------- helpers ----------------
__device__ __forceinline__ uint32_t smem_u32(const void* p) {
    uint32_t a;
    asm("{ .reg .u64 t; cvta.to.shared.u64 t, %1; cvt.u32.u64 %0, t; }" : "=r"(a) : "l"(p));
    return a;
}
__device__ __forceinline__ void cp16(uint32_t s, const void* g) {
    asm volatile("cp.async.cg.shared.global [%0], [%1], 16;" :: "r"(s), "l"(g));
}
__device__ __forceinline__ void mma_f16(float* d, uint32_t a0, uint32_t a1,
                                        uint32_t a2, uint32_t a3,
                                        uint32_t b0, uint32_t b1) {
    asm volatile(
        "mma.sync.aligned.m16n8k16.row.col.f32.f16.f16.f32 "
        "{%0,%1,%2,%3}, {%4,%5,%6,%7}, {%8,%9}, {%0,%1,%2,%3};"
        : "+f"(d[0]), "+f"(d[1]), "+f"(d[2]), "+f"(d[3])
        : "r"(a0), "r"(a1), "r"(a2), "r"(a3), "r"(b0), "r"(b1));
}

// ---------------- fp16 mma.sync GEMM (R13-exact mainloop) ----------------
// C[M,N] = scale * A[M,K] @ B[N,K]^T (+bias[n]); A,B fp16 K-major in half arena.
#define BM 128
#define BN 128
#define BKH 64
#define ROWB 160u
#define TILEB (128u * ROWB)
#define STAGEB (2u * TILEB)
#define SMEM_BYTES (2 * (int)STAGEB)   // 81920

template<int OUTH>
__global__ void __launch_bounds__(128, 2)
gemm_h(size_t aOff, size_t bOff, const float* bias,
       float* Cf, size_t cOff, int M, int N, int Kd, float scale,
       size_t sA, size_t sB, size_t sC)
{
    extern __shared__ char smc[];
    const __half* Ap = (const __half*)g_scratch + aOff + (size_t)blockIdx.z * sA;
    const __half* Bp = (const __half*)g_scratch + bOff + (size_t)blockIdx.z * sB;

    const int tid  = threadIdx.x;
    const int lane = tid & 31;
    const int wid  = tid >> 5;
    const int wm   = wid >> 1;
    const int wn   = wid & 1;
    const int grp  = lane >> 2;
    const int t4   = lane & 3;
    const int m0   = blockIdx.y * BM;
    const int n0   = blockIdx.x * BN;
    const uint32_t sbase = smem_u32(smc);

    float acc[4][8][4];
#pragma unroll
    for (int a = 0; a < 4; a++)
#pragma unroll
        for (int b = 0; b < 8; b++)
#pragma unroll
            for (int c = 0; c < 4; c++) acc[a][b][c] = 0.f;

    auto issue_tile = [&](int k0, int stg) {
        const uint32_t aB = sbase + (uint32_t)stg * STAGEB;
        const uint32_t bB = aB + TILEB;
#pragma unroll
        for (int j = 0; j < 8; j++) {
            int f  = tid + j * 128;
            int r  = f >> 3;
            int c  = f & 7;
            cp16(aB + (uint32_t)r * ROWB + (uint32_t)c * 16u,
                 Ap + (size_t)(m0 + r) * Kd + k0 + c * 8);
            cp16(bB + (uint32_t)r * ROWB + (uint32_t)c * 16u,
                 Bp + (size_t)(n0 + r) * Kd + k0 + c * 8);
        }
        asm volatile("cp.async.commit_group;" ::: "memory");
    };

    const int NT = Kd / BKH;
    issue_tile(0, 0);

    for (int i = 0; i < NT; i++) {
        if (i + 1 < NT) {
            issue_tile((i + 1) * BKH, (i + 1) & 1);
            asm volatile("cp.async.wait_group 1;" ::: "memory");
        } else {
            asm volatile("cp.async.wait_group 0;" ::: "memory");
        }
        __syncthreads();

        const char* As = smc + (i & 1) * STAGEB;
        const char* Bs = As + TILEB;

#pragma unroll
        for (int s = 0; s < 4; s++) {
            uint2 avLo[4], avHi[4], bv[8];
#pragma unroll
            for (int mt = 0; mt < 4; mt++) {
                const int row = wm * 64 + mt * 16 + grp;
                avLo[mt] = *reinterpret_cast<const uint2*>(
                    As + (size_t)row * ROWB + s * 32 + t4 * 8);
                avHi[mt] = *reinterpret_cast<const uint2*>(
                    As + (size_t)(row + 8) * ROWB + s * 32 + t4 * 8);
            }
#pragma unroll
            for (int nt = 0; nt < 8; nt++) {
                const int nr = wn * 64 + nt * 8 + grp;
                bv[nt] = *reinterpret_cast<const uint2*>(
                    Bs + (size_t)nr * ROWB + s * 32 + t4 * 8);
            }
#pragma unroll
            for (int mt = 0; mt < 4; mt++)
#pragma unroll
                for (int nt = 0; nt < 8; nt++)
                    mma_f16(acc[mt][nt],
                            avLo[mt].x, avHi[mt].x, avLo[mt].y, avHi[mt].y,
                            bv[nt].x, bv[nt].y);
        }
        __syncthreads();
    }

    // ---------------- epilogue ----------------
    __half* Ch = (__half*)g_scratch + cOff + (size_t)blockIdx.z * sC;
    float* Cp = nullptr;
    if (!OUTH) Cp = (Cf ? Cf : (g_scratch + cOff)) + (size_t)blockIdx.z * sC;

#pragma unroll
    for (int mt = 0; mt < 4; mt++) {
        const int m = m0 + wm * 64 + mt * 16 + grp;
#pragma unroll
        for (int nt = 0; nt < 8; nt++) {
            const int n = n0 + wn * 64 + nt * 8 + t4 * 2;
            float bx = 0.f, by = 0.f;
            if (bias) {
                const float2 bb = *reinterpret_cast<const float2*>(bias + n);
                bx = bb.x; by = bb.y;
            }
            const float v00 = acc[mt][nt][0] * scale + bx;
            const float v01 = acc[mt][nt][1] * scale + by;
            const float v10 = acc[mt][nt][2] * scale + bx;
            const float v11 = acc[mt][nt][3] * scale + by;
            if (OUTH) {
                *reinterpret_cast<__half2*>(Ch + (size_t)m * N + n) =
                    __floats2half2_rn(v00, v01);
                *reinterpret_cast<__half2*>(Ch + (size_t)(m + 8) * N + n) =
                    __floats2half2_rn(v10, v11);
            } else {
                *reinterpret_cast<float2*>(Cp + (size_t)m * N + n) = make_float2(v00, v01);
                *reinterpret_cast<float2*>(Cp + (size_t)(m + 8) * N + n) = make_float2(v10, v11);
            }
        }
    }
}

// ---------------- fp32 -> fp16 elementwise (z picks src tensor) ----------------
__global__ void __launch_bounds__(256)
cvt_f2h(const float* __restrict__ in0, const float* __restrict__ in1, size_t n)
{
    const float* in = blockIdx.z ? in1 : in0;
    const size_t hOff = H_QIN + (size_t)blockIdx.z * 16777216ull;
    const size_t i = ((size_t)blockIdx.x * 256 + threadIdx.x) * 4;
    if (i >= n) return;
    const float4 v = *reinterpret_cast<const float4*>(in + i);
    __half2* dst = reinterpret_cast<__half2*>((__half*)g_scratch + hOff + i);
    dst[0] = __floats2half2_rn(v.x, v.y);
    dst[1] = __floats2half2_rn(v.z, v.w);
}

// ---------------- fp32 -> fp16 weight transpose (z picks weight) ----------------
__global__ void __launch_bounds__(256)
cvtT_f2h(const float* W0, const float* W1, const float* W2, const float* W3)
{
    __shared__ float t[32][33];
    const float* in = (blockIdx.z == 0) ? W0 : (blockIdx.z == 1) ? W1
                    : (blockIdx.z == 2) ? W2 : W3;
    __half* op = (__half*)g_scratch + H_WQ + (size_t)blockIdx.z * 1048576ull;
    const int c0 = blockIdx.x * 32, r0 = blockIdx.y * 32;
    const int tx = threadIdx.x & 31, ty = threadIdx.x >> 5;
#pragma unroll
    for (int i = 0; i < 4; i++)
        t[ty + i * 8][tx] = in[(size_t)(r0 + ty + i * 8) * ED + c0 + tx];
    __syncthreads();
#pragma unroll
    for (int i = 0; i < 4; i++)
        op[(size_t)(c0 + ty + i * 8) * ED + r0 + tx] = __float2half(t[tx][ty + i * 8]);
}

// ---------------- fp16 transpose (V -> VT per batch) ----------------
__global__ void __launch_bounds__(256)
transpose_h(size_t inOff, size_t outOff, int R, int Cc, size_t sIn, size_t sOut)
{
    __shared__ __half t[32][34];
    const __half* ip = (const __half*)g_scratch + inOff + (size_t)blockIdx.z * sIn;
    __half*       op = (__half*)g_scratch + outOff + (size_t)blockIdx.z * sOut;
    const int c0 = blockIdx.x * 32, r0 = blockIdx.y * 32;
    const int tx = threadIdx.x & 31, ty = threadIdx.x >> 5;
#pragma unroll
    for (int i = 0; i < 4; i++)
        t[ty + i * 8][tx] = ip[(size_t)(r0 + ty + i * 8) * Cc + c0 + tx];
    __syncthreads();
#pragma unroll
    for (int i = 0; i < 4; i++)
        op[(size_t)(c0 + ty + i * 8) * R + r0 + tx] = t[tx][ty + i * 8];
}

// ---------------- masked softmax: vectorized, shuffle reductions ----------------
__global__ void __launch_bounds__(256)
softmax_mask_kernel(float* att, size_t attOff, const int* __restrict__ mask)
{
    float* base = att ? att : (g_scratch + attOff);
    const size_t row = blockIdx.x;
    float4* p4 = reinterpret_cast<float4*>(base + row * KLEN);
    const int4* m4 = reinterpret_cast<const int4*>(mask + row * KLEN);
    __half* ph = (__half*)g_scratch + H_ATT + row * KLEN;
    const int t = threadIdx.x;
    const int lane = t & 31, w = t >> 5;
    __shared__ float red[8];

    float4 v[2];
    float mx = -INFINITY;
#pragma unroll
    for (int i = 0; i < 2; i++) {
        const int c4 = t + i * 256;
        float4 x = p4[c4];
        const int4 mm = m4[c4];
        x.x = mm.x ? x.x : -INFINITY;
        x.y = mm.y ? x.y : -INFINITY;
        x.z = mm.z ? x.z : -INFINITY;
        x.w = mm.w ? x.w : -INFINITY;
        v[i] = x;
        mx = fmaxf(mx, fmaxf(fmaxf(x.x, x.y), fmaxf(x.z, x.w)));
    }
#pragma unroll
    for (int o = 16; o > 0; o >>= 1)
        mx = fmaxf(mx, __shfl_xor_sync(0xFFFFFFFFu, mx, o));
    if (lane == 0) red[w] = mx;
    __syncthreads();
    mx = red[lane & 7];
#pragma unroll
    for (int o = 4; o > 0; o >>= 1)
        mx = fmaxf(mx, __shfl_xor_sync(0xFFFFFFFFu, mx, o));

    float sum = 0.f;
#pragma unroll
    for (int i = 0; i < 2; i++) {
        v[i].x = __expf(v[i].x - mx); sum += v[i].x;
        v[i].y = __expf(v[i].y - mx); sum += v[i].y;
        v[i].z = __expf(v[i].z - mx); sum += v[i].z;
        v[i].w = __expf(v[i].w - mx); sum += v[i].w;
    }
#pragma unroll
    for (int o = 16; o > 0; o >>= 1)
        sum += __shfl_xor_sync(0xFFFFFFFFu, sum, o);
    __syncthreads();
    if (lane == 0) red[w] = sum;
    __syncthreads();
    sum = red[lane & 7];
#pragma unroll
    for (int o = 4; o > 0; o >>= 1)
        sum += __shfl_xor_sync(0xFFFFFFFFu, sum, o);
    const float inv = 1.f / sum;

#pragma unroll
    for (int i = 0; i < 2; i++) {
        const int c4 = t + i * 256;
        float4 x = v[i];
        x.x *= inv; x.y *= inv; x.z *= inv; x.w *= inv;
        p4[c4] = x;
        __half2 h0 = __floats2half2_rn(x.x, x.y);
        __half2 h1 = __floats2half2_rn(x.z, x.w);
        uint2 pk;
        pk.x = *reinterpret_cast<uint32_t*>(&h0);
        pk.y = *reinterpret_cast<uint32_t*>(&h1);
        *reinterpret_cast<uint2*>(ph + (size_t)c4 * 4) = pk;
    }
}

// ---------------- launch ----------------
extern "C" void kernel_launch(void* const* d_in, const int* in_sizes, int n_in,
                              void* d_out, int out_size)
{
    const float* query = (const float*)d_in[0];
    const float* keyv  = (const float*)d_in[1];
    const int*   mask  = (const int*)  d_in[2];
    const float* Wq = (const float*)d_in[3];
    const float* bq = (const float*)d_in[4];
    const float* Wk = (const float*)d_in[5];
    const float* bk = (const float*)d_in[6];
    const float* Wv = (const float*)d_in[7];
    const float* bv = (const float*)d_in[8];
    const float* Wo = (const float*)d_in[9];
    const float* bo = (const float*)d_in[10];

    float* out = (float*)d_out;
    const size_t out_elems = (size_t)NB * QL * ED;
    const bool attn_in_out = ((size_t)out_size > out_elems);
    float* attn_ptr = attn_in_out ? (out + out_elems) : nullptr;

    static bool attr_set = false;
    if (!attr_set) {
        cudaFuncSetAttribute(gemm_h<0>, cudaFuncAttributeMaxDynamicSharedMemorySize, SMEM_BYTES);
        cudaFuncSetAttribute(gemm_h<1>, cudaFuncAttributeMaxDynamicSharedMemorySize, SMEM_BYTES);
        attr_set = true;
    }

    const int M_ALL = NB * QL;
    const float scale = 1.0f / 32.0f;
    const size_t nIn = (size_t)M_ALL * ED;

    dim3 cvtG((unsigned)(nIn / 4 / 256), 1, 2);
    dim3 tposeW(ED / 32, ED / 32, 4);
    dim3 tposeV(ED / 32, KLEN / 32, NB);
    dim3 gProj (ED / BN,   M_ALL / BM, 1);
    dim3 gScore(KLEN / BN, QL / BM,    NB);
    dim3 gAV   (ED / BN,   QL / BM,    NB);

    // 0: converts (2 launches)
    cvt_f2h<<<cvtG, 256>>>(query, keyv, nIn);
    cvtT_f2h<<<tposeW, 256>>>(Wq, Wk, Wv, Wo);

    // 1-3: projections -> fp16 Q/K/V (R13-exact)
    gemm_h<1><<<gProj, 128, SMEM_BYTES>>>(H_QIN, H_WQ, bq, nullptr, H_Q,
                                          M_ALL, ED, ED, 1.0f, 0, 0, 0);
    gemm_h<1><<<gProj, 128, SMEM_BYTES>>>(H_KVIN, H_WK, bk, nullptr, H_K,
                                          M_ALL, ED, ED, 1.0f, 0, 0, 0);
    gemm_h<1><<<gProj, 128, SMEM_BYTES>>>(H_KVIN, H_WV, bv, nullptr, H_V,
                                          M_ALL, ED, ED, 1.0f, 0, 0, 0);

    // V^T per batch
    transpose_h<<<tposeV, 256>>>(H_V, H_VT, KLEN, ED,
                                 (size_t)KLEN * ED, (size_t)ED * KLEN);

    // 4: scores = scale * Q @ K^T -> fp32 attn
    gemm_h<0><<<gScore, 128, SMEM_BYTES>>>(H_Q, H_K, nullptr, attn_ptr, OFF_S,
                                           QL, KLEN, ED, scale,
                                           (size_t)QL * ED, (size_t)KLEN * ED,
                                           (size_t)QL * KLEN);

    // 5: masked softmax (fp32 in place + fp16 copy)
    softmax_mask_kernel<<<NB * QL, 256>>>(attn_ptr, OFF_S, mask);

    // 6: attended = attn @ V -> fp16
    gemm_h<1><<<gAV, 128, SMEM_BYTES>>>(H_ATT, H_VT, nullptr, nullptr, H_ATTD,
                                        QL, ED, KLEN, 1.0f,
                                        (size_t)QL * KLEN, (size_t)ED * KLEN,
                                        (size_t)QL * ED);

    // 7: out = attended @ Wo + bo -> fp32 d_out
    gemm_h<0><<<gProj, 128, SMEM_BYTES>>>(H_ATTD, H_WO, bo, out, 0,
                                          M_ALL, ED, ED, 1.0f, 0, 0, 0);
}